// round 10
// baseline (speedup 1.0000x reference)
#include <cuda_runtime.h>
#include <cuda_bf16.h>
#include <math.h>
#include <stdint.h>

#define S_  256
#define B_  64
#define E_  300
#define H_  512
#define G3  1536          // 3*H
#define NCLS 21

// ---------------- scratch (device globals; no allocation allowed) ----------------
__device__ float g_gi_f[(size_t)S_ * B_ * G3];     // [s][b][1536]
__device__ float g_gi_b[(size_t)S_ * B_ * G3];     // backward, time-reversed storage
__device__ float g_hf[(size_t)S_ * B_ * H_];       // fp32 h for head
__device__ float g_hb[(size_t)S_ * B_ * H_];
__device__ __nv_bfloat16 g_h16f[(size_t)S_ * B_ * H_];  // bf16 h for scan exchange
__device__ __nv_bfloat16 g_h16b[(size_t)S_ * B_ * H_];
__device__ unsigned g_cnt2[4 * 32];
__device__ unsigned g_gen2[4 * 32];

// ---------------- common helpers ----------------
__device__ __forceinline__ void mma_tf32(float c[4],
    uint32_t a0, uint32_t a1, uint32_t a2, uint32_t a3,
    uint32_t b0, uint32_t b1)
{
    asm volatile(
        "mma.sync.aligned.m16n8k8.row.col.f32.tf32.tf32.f32 "
        "{%0,%1,%2,%3},{%4,%5,%6,%7},{%8,%9},{%0,%1,%2,%3};"
        : "+f"(c[0]), "+f"(c[1]), "+f"(c[2]), "+f"(c[3])
        : "r"(a0), "r"(a1), "r"(a2), "r"(a3), "r"(b0), "r"(b1));
}

__device__ __forceinline__ void mma_bf16(float c[4],
    uint32_t a0, uint32_t a1, uint32_t a2, uint32_t a3,
    uint32_t b0, uint32_t b1)
{
    asm volatile(
        "mma.sync.aligned.m16n8k16.row.col.f32.bf16.bf16.f32 "
        "{%0,%1,%2,%3},{%4,%5,%6,%7},{%8,%9},{%0,%1,%2,%3};"
        : "+f"(c[0]), "+f"(c[1]), "+f"(c[2]), "+f"(c[3])
        : "r"(a0), "r"(a1), "r"(a2), "r"(a3), "r"(b0), "r"(b1));
}

__device__ __forceinline__ uint32_t f2tf32(float v) {
    uint32_t r;
    asm("cvt.rna.tf32.f32 %0, %1;" : "=r"(r) : "f"(v));
    return r;
}

// pack two floats into bf16x2: lo = first element (lower k), hi = second
__device__ __forceinline__ uint32_t pack_bf16(float lo, float hi) {
    uint32_t r;
    asm("cvt.rn.bf16x2.f32 %0, %1, %2;" : "=r"(r) : "f"(hi), "f"(lo));
    return r;
}

__device__ __forceinline__ unsigned atom_add_release(unsigned* p, unsigned v) {
    unsigned old;
    asm volatile("atom.add.release.gpu.global.u32 %0,[%1],%2;"
                 : "=r"(old) : "l"(p), "r"(v) : "memory");
    return old;
}

__device__ __forceinline__ unsigned ld_acquire(unsigned* p) {
    unsigned v;
    asm volatile("ld.acquire.gpu.global.u32 %0,[%1];" : "=r"(v) : "l"(p) : "memory");
    return v;
}

__device__ __forceinline__ float sigm_f(float x) {
    return __fdividef(1.f, 1.f + __expf(-x));
}
__device__ __forceinline__ float tanh_f(float x) {
    const float ax = fabsf(x);
    const float e  = __expf(-2.f * ax);
    const float r  = __fdividef(1.f - e, 1.f + e);
    return copysignf(r, x);
}

// =================================================================================
// Kernel A: gi = gather(emb, idx) @ W_ih^T + b_ih  — tf32 tensor-core GEMM.
// (unchanged from R6: 350us, tensor pipe 29%)
// =================================================================================
#define AP 136

__global__ void __launch_bounds__(256, 2) gi_gemm_kernel(
    const int* __restrict__ idxmat, const float* __restrict__ emb,
    const float* __restrict__ Wf, const float* __restrict__ bf,
    const float* __restrict__ Wb, const float* __restrict__ bbias)
{
    __shared__ uint32_t As[16][AP];
    __shared__ uint32_t Bs[16][AP];

    const int t    = threadIdx.x;
    const int n0   = blockIdx.x * 128;
    const int m0   = blockIdx.y * 128;
    const bool bwd = (n0 >= G3);

    const int lr = t & 127;
    const int lk = (t >> 7) * 8;

    const int am = m0 + lr;
    const int srow = am >> 6, brow = am & 63;
    const float* arow = emb + (size_t)idxmat[brow * S_ + srow] * E_;

    const int ng = n0 + lr;
    const float* wrow = bwd ? (Wb + (size_t)(ng - G3) * E_)
                            : (Wf + (size_t)ng * E_);

    const int lane = t & 31;
    const int w    = t >> 5;
    const int gq   = lane >> 2, tig = lane & 3;
    const int mw   = (w & 3) * 32;
    const int nw   = (w >> 2) * 64;

    float acc[2][8][4];
#pragma unroll
    for (int mt = 0; mt < 2; mt++)
#pragma unroll
        for (int nt = 0; nt < 8; nt++)
#pragma unroll
            for (int i = 0; i < 4; i++) acc[mt][nt][i] = 0.f;

    const float4 z4 = make_float4(0.f, 0.f, 0.f, 0.f);

    for (int k0 = 0; k0 < 304; k0 += 16) {
        const int ka = k0 + lk;
        float4 av0 = (ka     < E_) ? *(const float4*)(arow + ka)     : z4;
        float4 av1 = (ka + 4 < E_) ? *(const float4*)(arow + ka + 4) : z4;
        float4 bv0 = (ka     < E_) ? *(const float4*)(wrow + ka)     : z4;
        float4 bv1 = (ka + 4 < E_) ? *(const float4*)(wrow + ka + 4) : z4;
        __syncthreads();
        As[lk + 0][lr] = f2tf32(av0.x); As[lk + 1][lr] = f2tf32(av0.y);
        As[lk + 2][lr] = f2tf32(av0.z); As[lk + 3][lr] = f2tf32(av0.w);
        As[lk + 4][lr] = f2tf32(av1.x); As[lk + 5][lr] = f2tf32(av1.y);
        As[lk + 6][lr] = f2tf32(av1.z); As[lk + 7][lr] = f2tf32(av1.w);
        Bs[lk + 0][lr] = f2tf32(bv0.x); Bs[lk + 1][lr] = f2tf32(bv0.y);
        Bs[lk + 2][lr] = f2tf32(bv0.z); Bs[lk + 3][lr] = f2tf32(bv0.w);
        Bs[lk + 4][lr] = f2tf32(bv1.x); Bs[lk + 5][lr] = f2tf32(bv1.y);
        Bs[lk + 6][lr] = f2tf32(bv1.z); Bs[lk + 7][lr] = f2tf32(bv1.w);
        __syncthreads();

#pragma unroll
        for (int kt = 0; kt < 2; kt++) {
            const int kb = kt * 8;
            uint32_t a[2][4];
#pragma unroll
            for (int mt = 0; mt < 2; mt++) {
                const int mb = mw + mt * 16;
                a[mt][0] = As[kb + tig][mb + gq];
                a[mt][1] = As[kb + tig][mb + gq + 8];
                a[mt][2] = As[kb + tig + 4][mb + gq];
                a[mt][3] = As[kb + tig + 4][mb + gq + 8];
            }
#pragma unroll
            for (int nt = 0; nt < 8; nt++) {
                const int nb = nw + nt * 8 + gq;
                const uint32_t b0 = Bs[kb + tig][nb];
                const uint32_t b1 = Bs[kb + tig + 4][nb];
                mma_tf32(acc[0][nt], a[0][0], a[0][1], a[0][2], a[0][3], b0, b1);
                mma_tf32(acc[1][nt], a[1][0], a[1][1], a[1][2], a[1][3], b0, b1);
            }
        }
    }

    const float* bias = bwd ? bbias : bf;
    float* gbase = bwd ? g_gi_b : g_gi_f;
    const int nc0 = (bwd ? n0 - G3 : n0) + nw;

#pragma unroll
    for (int mt = 0; mt < 2; mt++) {
#pragma unroll
        for (int half = 0; half < 2; half++) {
            const int rm = m0 + mw + mt * 16 + gq + half * 8;
            const int si = rm >> 6, bi = rm & 63;
            const size_t mrow = bwd ? ((size_t)(S_ - 1 - si) * B_ + bi) : (size_t)rm;
            float* dst = gbase + mrow * G3;
#pragma unroll
            for (int nt = 0; nt < 8; nt++) {
                const int c = nc0 + nt * 8 + 2 * tig;
                float2 v;
                v.x = acc[mt][nt][half * 2 + 0] + bias[c];
                v.y = acc[mt][nt][half * 2 + 1] + bias[c + 1];
                *(float2*)(dst + c) = v;
            }
        }
    }
}

// =================================================================================
// Kernel B: persistent bidirectional GRU scan — bf16 m16n8k16 mma.
// 128 blocks = dir(2) x jblk(32: 16 units) x bhalf(2: 32 batch). 256 threads,
// 8 warps = k-eighth. Each warp: all 3 gates x 4 n-tiles from shared B-frags.
// W A-frags register-resident (bf16). h exchanged via gmem bf16; exact fp32
// h_prev slice kept in local smem 'hold'. acquire/release 32-block barriers.
// =================================================================================
#define KP 260                  // hs16 pitch in u32 (4*gq+tig banks -> conflict-free)
#define BUFP 34
#define HOLDP 17
#define SMEM_B_BYTES ((32 * KP + 8 * 48 * BUFP + 32 * HOLDP + 64) * 4)

__global__ void __launch_bounds__(256, 1) gru_scan_kernel(
    const float* __restrict__ Whh_f, const float* __restrict__ bhh_f,
    const float* __restrict__ Whh_b, const float* __restrict__ bhh_b)
{
    extern __shared__ float sm[];
    uint32_t* hs16 = (uint32_t*)sm;          // [32][KP] bf16x2 tile of h_prev
    float* buf  = sm + 32 * KP;              // [8*48][BUFP] mma partials
    float* hold = buf + 8 * 48 * BUFP;       // [32][HOLDP] own fp32 h_prev slice
    __shared__ float bbv[48];
    __shared__ unsigned sbase;

    const int t    = threadIdx.x;
    const int lane = t & 31;
    const int kg   = t >> 5;          // warp = k-eighth 0..7
    const int gq   = lane >> 2;
    const int tig  = lane & 3;

    const int blk   = blockIdx.x;
    const int dir   = blk >> 6;
    const int r     = blk & 63;
    const int jblk  = r >> 1;
    const int bhalf = r & 1;
    const int j0    = jblk * 16;
    const int b0    = bhalf * 32;
    const int grp   = dir * 2 + bhalf;

    const float* Whh = dir ? Whh_b : Whh_f;
    const float* bhh = dir ? bhh_b : bhh_f;
    const float* gi  = dir ? g_gi_b : g_gi_f;
    float* hout32    = dir ? g_hb : g_hf;
    __nv_bfloat16* hout16 = dir ? g_h16b : g_h16f;

    if (t < 48) bbv[t] = bhh[(size_t)((t >> 4) * 512 + j0 + (t & 15))];
    if (t == 0) sbase = *(volatile unsigned*)&g_gen2[grp * 32];

    // ---- register-resident bf16 A-fragments: a[g][kt][4] ----
    uint32_t a[3][4][4];
#pragma unroll
    for (int g = 0; g < 3; g++) {
        const float* Wg = Whh + (size_t)(g * 512 + j0) * 512;
#pragma unroll
        for (int kt = 0; kt < 4; kt++) {
            const int kb = kg * 64 + kt * 16;
            const int c0 = kb + 2 * tig;
            const int c1 = kb + 8 + 2 * tig;
            a[g][kt][0] = pack_bf16(Wg[(size_t)gq * 512 + c0],      Wg[(size_t)gq * 512 + c0 + 1]);
            a[g][kt][1] = pack_bf16(Wg[(size_t)(gq + 8) * 512 + c0], Wg[(size_t)(gq + 8) * 512 + c0 + 1]);
            a[g][kt][2] = pack_bf16(Wg[(size_t)gq * 512 + c1],      Wg[(size_t)gq * 512 + c1 + 1]);
            a[g][kt][3] = pack_bf16(Wg[(size_t)(gq + 8) * 512 + c1], Wg[(size_t)(gq + 8) * 512 + c1 + 1]);
        }
    }
    __syncthreads();

    // gate-combine coordinates: outputs o = t and o = t+256
    const int j1 = t & 15, b1 = t >> 4;          // b1 in 0..15
    const int b2 = b1 + 16;

    for (int s = 0; s < S_; ++s) {
        // ---- prefetch gi[s] (overlaps barrier wait) ----
        const float* gis = gi + (size_t)s * (B_ * G3);
        const size_t ga1 = (size_t)(b0 + b1) * G3 + j0 + j1;
        const size_t ga2 = (size_t)(b0 + b2) * G3 + j0 + j1;
        const float ir0 = gis[ga1], iz0 = gis[ga1 + 512], in0 = gis[ga1 + 1024];
        const float ir1 = gis[ga2], iz1 = gis[ga2 + 512], in1 = gis[ga2 + 1024];

        if (s > 0) {
            // ---- wait for h16[s-1] from all 32 group blocks ----
            if (t == 0) {
                const unsigned tgt = sbase + (unsigned)s;
                while (ld_acquire(&g_gen2[grp * 32]) < tgt) { }
            }
            __syncthreads();

            // ---- stage bf16 h tile: straight uint4 copy, 32 rows x 512 bf16 ----
            const uint4* hsrc = (const uint4*)(g_h16f + 0) /*placeholder*/;
            hsrc = (const uint4*)(hout16 + (size_t)(s - 1) * (B_ * H_) + (size_t)b0 * H_);
#pragma unroll 2
            for (int i = t; i < 2048; i += 256) {
                const int b = i >> 6, c = i & 63;
                ((uint4*)hs16)[b * (KP / 4) + c] = hsrc[b * 64 + c];
            }
            __syncthreads();

            // ---- mma: 3 gates x 4 n-tiles, B-frags shared across gates ----
            float acc[3][4][4];
#pragma unroll
            for (int g = 0; g < 3; g++)
#pragma unroll
                for (int nt = 0; nt < 4; nt++)
#pragma unroll
                    for (int i = 0; i < 4; i++) acc[g][nt][i] = 0.f;

#pragma unroll
            for (int kt = 0; kt < 4; kt++) {
#pragma unroll
                for (int nt = 0; nt < 4; nt++) {
                    const int base = (nt * 8 + gq) * KP + kg * 32 + kt * 8 + tig;
                    const uint32_t bb0 = hs16[base];
                    const uint32_t bb1 = hs16[base + 4];
#pragma unroll
                    for (int g = 0; g < 3; g++)
                        mma_bf16(acc[g][nt], a[g][kt][0], a[g][kt][1],
                                 a[g][kt][2], a[g][kt][3], bb0, bb1);
                }
            }
            // store partials
#pragma unroll
            for (int g = 0; g < 3; g++) {
                float* bb = buf + (size_t)(kg * 48 + g * 16) * BUFP;
#pragma unroll
                for (int nt = 0; nt < 4; nt++) {
                    const int c = nt * 8 + 2 * tig;
                    float2 lo = make_float2(acc[g][nt][0], acc[g][nt][1]);
                    float2 hi = make_float2(acc[g][nt][2], acc[g][nt][3]);
                    *(float2*)(bb + gq * BUFP + c)       = lo;
                    *(float2*)(bb + (gq + 8) * BUFP + c) = hi;
                }
            }
            __syncthreads();
        }

        // ---- gate combine: 2 outputs per thread ----
        float* hnew32 = hout32 + (size_t)s * (B_ * H_);
        __nv_bfloat16* hnew16 = hout16 + (size_t)s * (B_ * H_);
        {
            float rs = 0.f, zs = 0.f, ns = 0.f, hp = 0.f;
            if (s > 0) {
#pragma unroll
                for (int q = 0; q < 8; q++) {
                    rs += buf[(q * 48 + j1) * BUFP + b1];
                    zs += buf[(q * 48 + 16 + j1) * BUFP + b1];
                    ns += buf[(q * 48 + 32 + j1) * BUFP + b1];
                }
                hp = hold[b1 * HOLDP + j1];
            }
            const float rg = sigm_f(ir0 + rs + bbv[j1]);
            const float zg = sigm_f(iz0 + zs + bbv[16 + j1]);
            const float ng = tanh_f(in0 + rg * (ns + bbv[32 + j1]));
            const float hv = (1.f - zg) * ng + zg * hp;
            hnew32[(size_t)(b0 + b1) * H_ + j0 + j1] = hv;
            hnew16[(size_t)(b0 + b1) * H_ + j0 + j1] = __float2bfloat16(hv);
            hold[b1 * HOLDP + j1] = hv;
        }
        {
            float rs = 0.f, zs = 0.f, ns = 0.f, hp = 0.f;
            if (s > 0) {
#pragma unroll
                for (int q = 0; q < 8; q++) {
                    rs += buf[(q * 48 + j1) * BUFP + b2];
                    zs += buf[(q * 48 + 16 + j1) * BUFP + b2];
                    ns += buf[(q * 48 + 32 + j1) * BUFP + b2];
                }
                hp = hold[b2 * HOLDP + j1];
            }
            const float rg = sigm_f(ir1 + rs + bbv[j1]);
            const float zg = sigm_f(iz1 + zs + bbv[16 + j1]);
            const float ng = tanh_f(in1 + rg * (ns + bbv[32 + j1]));
            const float hv = (1.f - zg) * ng + zg * hp;
            hnew32[(size_t)(b0 + b2) * H_ + j0 + j1] = hv;
            hnew16[(size_t)(b0 + b2) * H_ + j0 + j1] = __float2bfloat16(hv);
            hold[b2 * HOLDP + j1] = hv;
        }

        // ---- arrive (release) ----
        if (s < S_ - 1) {
            __syncthreads();
            if (t == 0) {
                const unsigned old = atom_add_release(&g_cnt2[grp * 32], 1u);
                if (old == 31u) {
                    *(volatile unsigned*)&g_cnt2[grp * 32] = 0u;
                    atom_add_release(&g_gen2[grp * 32], 1u);
                }
            }
        }
    }
}

// =================================================================================
// Kernel C: logits + log_softmax + transpose to [B,21,S]  [unchanged]
// =================================================================================
#define SMEM_C_BYTES ((NCLS * 1024 + 1024 + 32) * 4)

__global__ void __launch_bounds__(256, 1) head_kernel(
    const float* __restrict__ linW, const float* __restrict__ linb,
    float* __restrict__ out)
{
    extern __shared__ float sm[];
    float* Wsm = sm;
    float* row = Wsm + NCLS * 1024;
    float* lg  = row + 1024;

    const int t = threadIdx.x;
    for (int i = t; i < NCLS * 1024; i += 256) Wsm[i] = linW[i];
    __syncthreads();

    const int w = t >> 5, lane = t & 31;
    const int m0 = blockIdx.x * 16;

    for (int rr = 0; rr < 16; rr++) {
        const int m = m0 + rr;
        const int s = m >> 6, b = m & 63;
        const float* hf = g_hf + ((size_t)s * B_ + b) * H_;
        const float* hb = g_hb + ((size_t)(S_ - 1 - s) * B_ + b) * H_;
        ((float4*)row)[t] = (t < 128) ? ((const float4*)hf)[t]
                                      : ((const float4*)hb)[t - 128];
        __syncthreads();

#pragma unroll
        for (int j = 0; j < 3; j++) {
            const int c = w + 8 * j;
            if (c < NCLS) {
                float p = 0.f;
                const float* wc = Wsm + c * 1024;
#pragma unroll 4
                for (int k = lane; k < 1024; k += 32) p = fmaf(row[k], wc[k], p);
#pragma unroll
                for (int off = 16; off; off >>= 1) p += __shfl_xor_sync(0xffffffffu, p, off);
                if (lane == 0) lg[c] = p + linb[c];
            }
        }
        __syncthreads();
        if (t == 0) {
            float mx = lg[0];
            for (int c = 1; c < NCLS; c++) mx = fmaxf(mx, lg[c]);
            float sum = 0.f;
            for (int c = 0; c < NCLS; c++) sum += __expf(lg[c] - mx);
            lg[24] = mx + __logf(sum);
        }
        __syncthreads();
        if (t < NCLS)
            out[(size_t)b * (NCLS * S_) + (size_t)t * S_ + s] = lg[t] - lg[24];
        __syncthreads();
    }
}

// =================================================================================
extern "C" void kernel_launch(void* const* d_in, const int* in_sizes, int n_in,
                              void* d_out, int out_size)
{
    (void)in_sizes; (void)n_in; (void)out_size;
    const int*   idx     = (const int*)  d_in[0];
    const float* emb     = (const float*)d_in[1];
    const float* W_ih_f  = (const float*)d_in[2];
    const float* W_hh_f  = (const float*)d_in[3];
    const float* b_ih_f  = (const float*)d_in[4];
    const float* b_hh_f  = (const float*)d_in[5];
    const float* W_ih_b  = (const float*)d_in[6];
    const float* W_hh_b  = (const float*)d_in[7];
    const float* b_ih_b  = (const float*)d_in[8];
    const float* b_hh_b  = (const float*)d_in[9];
    const float* lin_W   = (const float*)d_in[10];
    const float* lin_b   = (const float*)d_in[11];
    float* out = (float*)d_out;

    cudaFuncSetAttribute(gru_scan_kernel, cudaFuncAttributeMaxDynamicSharedMemorySize, SMEM_B_BYTES);
    cudaFuncSetAttribute(head_kernel,     cudaFuncAttributeMaxDynamicSharedMemorySize, SMEM_C_BYTES);

    dim3 gA(24, 128);
    gi_gemm_kernel<<<gA, 256>>>(idx, emb, W_ih_f, b_ih_f, W_ih_b, b_ih_b);
    gru_scan_kernel<<<128, 256, SMEM_B_BYTES>>>(W_hh_f, b_hh_f, W_hh_b, b_hh_b);
    head_kernel<<<1024, 256, SMEM_C_BYTES>>>(lin_W, lin_b, out);
}

// round 11
// speedup vs baseline: 1.2206x; 1.2206x over previous
#include <cuda_runtime.h>
#include <cuda_bf16.h>
#include <math.h>
#include <stdint.h>

#define S_  256
#define B_  64
#define E_  300
#define H_  512
#define G3  1536          // 3*H
#define NCLS 21

// ---------------- scratch (device globals; no allocation allowed) ----------------
__device__ float g_gi_f[(size_t)S_ * B_ * G3];     // [s][b][1536]
__device__ float g_gi_b[(size_t)S_ * B_ * G3];     // backward, time-reversed storage
__device__ float g_hf[(size_t)S_ * B_ * H_];       // fp32 h for head
__device__ float g_hb[(size_t)S_ * B_ * H_];
__device__ __nv_bfloat16 g_h16f[(size_t)S_ * B_ * H_];  // bf16 h for scan exchange
__device__ __nv_bfloat16 g_h16b[(size_t)S_ * B_ * H_];
// per-producer monotonic flags: [dir][bhalf][jblk][pad]
__device__ unsigned g_flag[2][2][32][8];

// ---------------- common helpers ----------------
__device__ __forceinline__ void mma_tf32(float c[4],
    uint32_t a0, uint32_t a1, uint32_t a2, uint32_t a3,
    uint32_t b0, uint32_t b1)
{
    asm volatile(
        "mma.sync.aligned.m16n8k8.row.col.f32.tf32.tf32.f32 "
        "{%0,%1,%2,%3},{%4,%5,%6,%7},{%8,%9},{%0,%1,%2,%3};"
        : "+f"(c[0]), "+f"(c[1]), "+f"(c[2]), "+f"(c[3])
        : "r"(a0), "r"(a1), "r"(a2), "r"(a3), "r"(b0), "r"(b1));
}

__device__ __forceinline__ void mma_bf16(float c[4],
    uint32_t a0, uint32_t a1, uint32_t a2, uint32_t a3,
    uint32_t b0, uint32_t b1)
{
    asm volatile(
        "mma.sync.aligned.m16n8k16.row.col.f32.bf16.bf16.f32 "
        "{%0,%1,%2,%3},{%4,%5,%6,%7},{%8,%9},{%0,%1,%2,%3};"
        : "+f"(c[0]), "+f"(c[1]), "+f"(c[2]), "+f"(c[3])
        : "r"(a0), "r"(a1), "r"(a2), "r"(a3), "r"(b0), "r"(b1));
}

__device__ __forceinline__ uint32_t f2tf32(float v) {
    uint32_t r;
    asm("cvt.rna.tf32.f32 %0, %1;" : "=r"(r) : "f"(v));
    return r;
}

__device__ __forceinline__ uint32_t pack_bf16(float lo, float hi) {
    uint32_t r;
    asm("cvt.rn.bf16x2.f32 %0, %1, %2;" : "=r"(r) : "f"(hi), "f"(lo));
    return r;
}

__device__ __forceinline__ unsigned ld_acquire(unsigned* p) {
    unsigned v;
    asm volatile("ld.acquire.gpu.global.u32 %0,[%1];" : "=r"(v) : "l"(p) : "memory");
    return v;
}

__device__ __forceinline__ void st_release(unsigned* p, unsigned v) {
    asm volatile("st.release.gpu.global.u32 [%0],%1;" :: "l"(p), "r"(v) : "memory");
}

__device__ __forceinline__ float sigm_f(float x) {
    return __fdividef(1.f, 1.f + __expf(-x));
}
__device__ __forceinline__ float tanh_f(float x) {
    const float ax = fabsf(x);
    const float e  = __expf(-2.f * ax);
    const float r  = __fdividef(1.f - e, 1.f + e);
    return copysignf(r, x);
}

// =================================================================================
// Kernel A: gi = gather(emb, idx) @ W_ih^T + b_ih  — tf32 tensor-core GEMM.
// (unchanged: 350us)
// =================================================================================
#define AP 136

__global__ void __launch_bounds__(256, 2) gi_gemm_kernel(
    const int* __restrict__ idxmat, const float* __restrict__ emb,
    const float* __restrict__ Wf, const float* __restrict__ bf,
    const float* __restrict__ Wb, const float* __restrict__ bbias)
{
    __shared__ uint32_t As[16][AP];
    __shared__ uint32_t Bs[16][AP];

    const int t    = threadIdx.x;
    const int n0   = blockIdx.x * 128;
    const int m0   = blockIdx.y * 128;
    const bool bwd = (n0 >= G3);

    const int lr = t & 127;
    const int lk = (t >> 7) * 8;

    const int am = m0 + lr;
    const int srow = am >> 6, brow = am & 63;
    const float* arow = emb + (size_t)idxmat[brow * S_ + srow] * E_;

    const int ng = n0 + lr;
    const float* wrow = bwd ? (Wb + (size_t)(ng - G3) * E_)
                            : (Wf + (size_t)ng * E_);

    const int lane = t & 31;
    const int w    = t >> 5;
    const int gq   = lane >> 2, tig = lane & 3;
    const int mw   = (w & 3) * 32;
    const int nw   = (w >> 2) * 64;

    float acc[2][8][4];
#pragma unroll
    for (int mt = 0; mt < 2; mt++)
#pragma unroll
        for (int nt = 0; nt < 8; nt++)
#pragma unroll
            for (int i = 0; i < 4; i++) acc[mt][nt][i] = 0.f;

    const float4 z4 = make_float4(0.f, 0.f, 0.f, 0.f);

    for (int k0 = 0; k0 < 304; k0 += 16) {
        const int ka = k0 + lk;
        float4 av0 = (ka     < E_) ? *(const float4*)(arow + ka)     : z4;
        float4 av1 = (ka + 4 < E_) ? *(const float4*)(arow + ka + 4) : z4;
        float4 bv0 = (ka     < E_) ? *(const float4*)(wrow + ka)     : z4;
        float4 bv1 = (ka + 4 < E_) ? *(const float4*)(wrow + ka + 4) : z4;
        __syncthreads();
        As[lk + 0][lr] = f2tf32(av0.x); As[lk + 1][lr] = f2tf32(av0.y);
        As[lk + 2][lr] = f2tf32(av0.z); As[lk + 3][lr] = f2tf32(av0.w);
        As[lk + 4][lr] = f2tf32(av1.x); As[lk + 5][lr] = f2tf32(av1.y);
        As[lk + 6][lr] = f2tf32(av1.z); As[lk + 7][lr] = f2tf32(av1.w);
        Bs[lk + 0][lr] = f2tf32(bv0.x); Bs[lk + 1][lr] = f2tf32(bv0.y);
        Bs[lk + 2][lr] = f2tf32(bv0.z); Bs[lk + 3][lr] = f2tf32(bv0.w);
        Bs[lk + 4][lr] = f2tf32(bv1.x); Bs[lk + 5][lr] = f2tf32(bv1.y);
        Bs[lk + 6][lr] = f2tf32(bv1.z); Bs[lk + 7][lr] = f2tf32(bv1.w);
        __syncthreads();

#pragma unroll
        for (int kt = 0; kt < 2; kt++) {
            const int kb = kt * 8;
            uint32_t a[2][4];
#pragma unroll
            for (int mt = 0; mt < 2; mt++) {
                const int mb = mw + mt * 16;
                a[mt][0] = As[kb + tig][mb + gq];
                a[mt][1] = As[kb + tig][mb + gq + 8];
                a[mt][2] = As[kb + tig + 4][mb + gq];
                a[mt][3] = As[kb + tig + 4][mb + gq + 8];
            }
#pragma unroll
            for (int nt = 0; nt < 8; nt++) {
                const int nb = nw + nt * 8 + gq;
                const uint32_t b0 = Bs[kb + tig][nb];
                const uint32_t b1 = Bs[kb + tig + 4][nb];
                mma_tf32(acc[0][nt], a[0][0], a[0][1], a[0][2], a[0][3], b0, b1);
                mma_tf32(acc[1][nt], a[1][0], a[1][1], a[1][2], a[1][3], b0, b1);
            }
        }
    }

    const float* bias = bwd ? bbias : bf;
    float* gbase = bwd ? g_gi_b : g_gi_f;
    const int nc0 = (bwd ? n0 - G3 : n0) + nw;

#pragma unroll
    for (int mt = 0; mt < 2; mt++) {
#pragma unroll
        for (int half = 0; half < 2; half++) {
            const int rm = m0 + mw + mt * 16 + gq + half * 8;
            const int si = rm >> 6, bi = rm & 63;
            const size_t mrow = bwd ? ((size_t)(S_ - 1 - si) * B_ + bi) : (size_t)rm;
            float* dst = gbase + mrow * G3;
#pragma unroll
            for (int nt = 0; nt < 8; nt++) {
                const int c = nc0 + nt * 8 + 2 * tig;
                float2 v;
                v.x = acc[mt][nt][half * 2 + 0] + bias[c];
                v.y = acc[mt][nt][half * 2 + 1] + bias[c + 1];
                *(float2*)(dst + c) = v;
            }
        }
    }
}

// =================================================================================
// Kernel B: persistent bidirectional GRU scan — bf16 mma + per-producer dataflow
// flags. 128 blocks = dir(2) x jblk(32) x bhalf(2). 8 warps = k-eighth; each warp
// polls only its 4 producer flags, stages its own 4KB k-slice, and runs mma with
// no block barrier. Single st.release per block per step; no atomics.
// =================================================================================
#define KP 260                  // hs16 pitch in u32
#define BUFP 34
#define HOLDP 17
#define SMEM_B_BYTES ((32 * KP + 8 * 48 * BUFP + 32 * HOLDP + 64) * 4)

__global__ void __launch_bounds__(256, 1) gru_scan_kernel(
    const float* __restrict__ Whh_f, const float* __restrict__ bhh_f,
    const float* __restrict__ Whh_b, const float* __restrict__ bhh_b)
{
    extern __shared__ float sm[];
    uint32_t* hs16 = (uint32_t*)sm;          // [32][KP] bf16x2 tile of h_prev
    float* buf  = sm + 32 * KP;              // [8*48][BUFP] mma partials
    float* hold = buf + 8 * 48 * BUFP;       // [32][HOLDP] own fp32 h_prev slice
    __shared__ float bbv[48];
    __shared__ unsigned sbase;

    const int t    = threadIdx.x;
    const int lane = t & 31;
    const int kg   = t >> 5;          // warp = k-eighth 0..7
    const int gq   = lane >> 2;
    const int tig  = lane & 3;

    const int blk   = blockIdx.x;
    const int dir   = blk >> 6;
    const int r     = blk & 63;
    const int jblk  = r >> 1;
    const int bhalf = r & 1;
    const int j0    = jblk * 16;
    const int b0    = bhalf * 32;

    const float* Whh = dir ? Whh_b : Whh_f;
    const float* bhh = dir ? bhh_b : bhh_f;
    const float* gi  = dir ? g_gi_b : g_gi_f;
    float* hout32    = dir ? g_hb : g_hf;
    __nv_bfloat16* hout16 = dir ? g_h16b : g_h16f;

    if (t < 48) bbv[t] = bhh[(size_t)((t >> 4) * 512 + j0 + (t & 15))];
    if (t == 0) sbase = *(volatile unsigned*)&g_flag[dir][bhalf][jblk][0];

    // ---- register-resident bf16 A-fragments: a[g][kt][4] ----
    uint32_t a[3][4][4];
#pragma unroll
    for (int g = 0; g < 3; g++) {
        const float* Wg = Whh + (size_t)(g * 512 + j0) * 512;
#pragma unroll
        for (int kt = 0; kt < 4; kt++) {
            const int kb = kg * 64 + kt * 16;
            const int c0 = kb + 2 * tig;
            const int c1 = kb + 8 + 2 * tig;
            a[g][kt][0] = pack_bf16(Wg[(size_t)gq * 512 + c0],      Wg[(size_t)gq * 512 + c0 + 1]);
            a[g][kt][1] = pack_bf16(Wg[(size_t)(gq + 8) * 512 + c0], Wg[(size_t)(gq + 8) * 512 + c0 + 1]);
            a[g][kt][2] = pack_bf16(Wg[(size_t)gq * 512 + c1],      Wg[(size_t)gq * 512 + c1 + 1]);
            a[g][kt][3] = pack_bf16(Wg[(size_t)(gq + 8) * 512 + c1], Wg[(size_t)(gq + 8) * 512 + c1 + 1]);
        }
    }
    __syncthreads();

    const unsigned sb = sbase;

    // gate-combine coordinates: outputs o = t and o = t+256
    const int j1 = t & 15, b1 = t >> 4;          // b1 in 0..15
    const int b2 = b1 + 16;

    // per-warp staging coordinates
    const int srow4 = lane >> 3;                  // 0..3 (row group within iter)
    const int scq   = lane & 7;                   // uint4 column 0..7

    for (int s = 0; s < S_; ++s) {
        // ---- prefetch gi[s] (overlaps flag wait) ----
        const float* gis = gi + (size_t)s * (B_ * G3);
        const size_t ga1 = (size_t)(b0 + b1) * G3 + j0 + j1;
        const size_t ga2 = (size_t)(b0 + b2) * G3 + j0 + j1;
        const float ir0 = gis[ga1], iz0 = gis[ga1 + 512], in0 = gis[ga1 + 1024];
        const float ir1 = gis[ga2], iz1 = gis[ga2 + 512], in1 = gis[ga2 + 1024];

        if (s > 0) {
            // ---- per-warp: wait for this warp's 4 producer blocks only ----
            const unsigned tgt = sb + (unsigned)s;
            if (lane < 4) {
                unsigned* fp = &g_flag[dir][bhalf][4 * kg + lane][0];
                while (ld_acquire(fp) < tgt) { }
            }
            __syncwarp();

            // ---- per-warp: stage own 4KB k-slice (32 rows x 32 u32) ----
            const uint4* hsrc = (const uint4*)(hout16 + (size_t)(s - 1) * (B_ * H_)
                                               + (size_t)b0 * H_);
            uint4* hdst = (uint4*)hs16;
#pragma unroll
            for (int i = 0; i < 8; i++) {
                const int row = i * 4 + srow4;
                hdst[row * (KP / 4) + kg * 8 + scq] = hsrc[row * 64 + kg * 8 + scq];
            }
            __syncwarp();

            // ---- mma: 3 gates x 4 n-tiles from own slice (no block sync) ----
            float acc[3][4][4];
#pragma unroll
            for (int g = 0; g < 3; g++)
#pragma unroll
                for (int nt = 0; nt < 4; nt++)
#pragma unroll
                    for (int i = 0; i < 4; i++) acc[g][nt][i] = 0.f;

#pragma unroll
            for (int kt = 0; kt < 4; kt++) {
#pragma unroll
                for (int nt = 0; nt < 4; nt++) {
                    const int base = (nt * 8 + gq) * KP + kg * 32 + kt * 8 + tig;
                    const uint32_t bb0 = hs16[base];
                    const uint32_t bb1 = hs16[base + 4];
#pragma unroll
                    for (int g = 0; g < 3; g++)
                        mma_bf16(acc[g][nt], a[g][kt][0], a[g][kt][1],
                                 a[g][kt][2], a[g][kt][3], bb0, bb1);
                }
            }
#pragma unroll
            for (int g = 0; g < 3; g++) {
                float* bb = buf + (size_t)(kg * 48 + g * 16) * BUFP;
#pragma unroll
                for (int nt = 0; nt < 4; nt++) {
                    const int c = nt * 8 + 2 * tig;
                    *(float2*)(bb + gq * BUFP + c)       = make_float2(acc[g][nt][0], acc[g][nt][1]);
                    *(float2*)(bb + (gq + 8) * BUFP + c) = make_float2(acc[g][nt][2], acc[g][nt][3]);
                }
            }
            __syncthreads();
        }

        // ---- gate combine: 2 outputs per thread ----
        float* hnew32 = hout32 + (size_t)s * (B_ * H_);
        __nv_bfloat16* hnew16 = hout16 + (size_t)s * (B_ * H_);
        {
            float rs = 0.f, zs = 0.f, ns = 0.f, hp = 0.f;
            if (s > 0) {
#pragma unroll
                for (int q = 0; q < 8; q++) {
                    rs += buf[(q * 48 + j1) * BUFP + b1];
                    zs += buf[(q * 48 + 16 + j1) * BUFP + b1];
                    ns += buf[(q * 48 + 32 + j1) * BUFP + b1];
                }
                hp = hold[b1 * HOLDP + j1];
            }
            const float rg = sigm_f(ir0 + rs + bbv[j1]);
            const float zg = sigm_f(iz0 + zs + bbv[16 + j1]);
            const float ng = tanh_f(in0 + rg * (ns + bbv[32 + j1]));
            const float hv = (1.f - zg) * ng + zg * hp;
            hnew32[(size_t)(b0 + b1) * H_ + j0 + j1] = hv;
            hnew16[(size_t)(b0 + b1) * H_ + j0 + j1] = __float2bfloat16(hv);
            hold[b1 * HOLDP + j1] = hv;
        }
        {
            float rs = 0.f, zs = 0.f, ns = 0.f, hp = 0.f;
            if (s > 0) {
#pragma unroll
                for (int q = 0; q < 8; q++) {
                    rs += buf[(q * 48 + j1) * BUFP + b2];
                    zs += buf[(q * 48 + 16 + j1) * BUFP + b2];
                    ns += buf[(q * 48 + 32 + j1) * BUFP + b2];
                }
                hp = hold[b2 * HOLDP + j1];
            }
            const float rg = sigm_f(ir1 + rs + bbv[j1]);
            const float zg = sigm_f(iz1 + zs + bbv[16 + j1]);
            const float ng = tanh_f(in1 + rg * (ns + bbv[32 + j1]));
            const float hv = (1.f - zg) * ng + zg * hp;
            hnew32[(size_t)(b0 + b2) * H_ + j0 + j1] = hv;
            hnew16[(size_t)(b0 + b2) * H_ + j0 + j1] = __float2bfloat16(hv);
            hold[b2 * HOLDP + j1] = hv;
        }

        // ---- publish own slice: one release store, no atomics ----
        if (s < S_ - 1) {
            __syncthreads();
            if (t == 0)
                st_release(&g_flag[dir][bhalf][jblk][0], sb + (unsigned)s + 1u);
        }
    }
}

// =================================================================================
// Kernel C: logits + log_softmax + transpose to [B,21,S]  [unchanged]
// =================================================================================
#define SMEM_C_BYTES ((NCLS * 1024 + 1024 + 32) * 4)

__global__ void __launch_bounds__(256, 1) head_kernel(
    const float* __restrict__ linW, const float* __restrict__ linb,
    float* __restrict__ out)
{
    extern __shared__ float sm[];
    float* Wsm = sm;
    float* row = Wsm + NCLS * 1024;
    float* lg  = row + 1024;

    const int t = threadIdx.x;
    for (int i = t; i < NCLS * 1024; i += 256) Wsm[i] = linW[i];
    __syncthreads();

    const int w = t >> 5, lane = t & 31;
    const int m0 = blockIdx.x * 16;

    for (int rr = 0; rr < 16; rr++) {
        const int m = m0 + rr;
        const int s = m >> 6, b = m & 63;
        const float* hf = g_hf + ((size_t)s * B_ + b) * H_;
        const float* hb = g_hb + ((size_t)(S_ - 1 - s) * B_ + b) * H_;
        ((float4*)row)[t] = (t < 128) ? ((const float4*)hf)[t]
                                      : ((const float4*)hb)[t - 128];
        __syncthreads();

#pragma unroll
        for (int j = 0; j < 3; j++) {
            const int c = w + 8 * j;
            if (c < NCLS) {
                float p = 0.f;
                const float* wc = Wsm + c * 1024;
#pragma unroll 4
                for (int k = lane; k < 1024; k += 32) p = fmaf(row[k], wc[k], p);
#pragma unroll
                for (int off = 16; off; off >>= 1) p += __shfl_xor_sync(0xffffffffu, p, off);
                if (lane == 0) lg[c] = p + linb[c];
            }
        }
        __syncthreads();
        if (t == 0) {
            float mx = lg[0];
            for (int c = 1; c < NCLS; c++) mx = fmaxf(mx, lg[c]);
            float sum = 0.f;
            for (int c = 0; c < NCLS; c++) sum += __expf(lg[c] - mx);
            lg[24] = mx + __logf(sum);
        }
        __syncthreads();
        if (t < NCLS)
            out[(size_t)b * (NCLS * S_) + (size_t)t * S_ + s] = lg[t] - lg[24];
        __syncthreads();
    }
}

// =================================================================================
extern "C" void kernel_launch(void* const* d_in, const int* in_sizes, int n_in,
                              void* d_out, int out_size)
{
    (void)in_sizes; (void)n_in; (void)out_size;
    const int*   idx     = (const int*)  d_in[0];
    const float* emb     = (const float*)d_in[1];
    const float* W_ih_f  = (const float*)d_in[2];
    const float* W_hh_f  = (const float*)d_in[3];
    const float* b_ih_f  = (const float*)d_in[4];
    const float* b_hh_f  = (const float*)d_in[5];
    const float* W_ih_b  = (const float*)d_in[6];
    const float* W_hh_b  = (const float*)d_in[7];
    const float* b_ih_b  = (const float*)d_in[8];
    const float* b_hh_b  = (const float*)d_in[9];
    const float* lin_W   = (const float*)d_in[10];
    const float* lin_b   = (const float*)d_in[11];
    float* out = (float*)d_out;

    cudaFuncSetAttribute(gru_scan_kernel, cudaFuncAttributeMaxDynamicSharedMemorySize, SMEM_B_BYTES);
    cudaFuncSetAttribute(head_kernel,     cudaFuncAttributeMaxDynamicSharedMemorySize, SMEM_C_BYTES);

    dim3 gA(24, 128);
    gi_gemm_kernel<<<gA, 256>>>(idx, emb, W_ih_f, b_ih_f, W_ih_b, b_ih_b);
    gru_scan_kernel<<<128, 256, SMEM_B_BYTES>>>(W_hh_f, b_hh_f, W_hh_b, b_hh_b);
    head_kernel<<<1024, 256, SMEM_C_BYTES>>>(lin_W, lin_b, out);
}

// round 12
// speedup vs baseline: 1.2435x; 1.0188x over previous
#include <cuda_runtime.h>
#include <cuda_bf16.h>
#include <math.h>
#include <stdint.h>

#define S_  256
#define B_  64
#define E_  300
#define H_  512
#define G3  1536          // 3*H
#define NCLS 21

// ---------------- scratch (device globals; no allocation allowed) ----------------
__device__ float g_gi_f[(size_t)S_ * B_ * G3];     // [s][b][1536]
__device__ float g_gi_b[(size_t)S_ * B_ * G3];     // backward, time-reversed storage
__device__ float g_hf[(size_t)S_ * B_ * H_];       // fp32 h for head
__device__ float g_hb[(size_t)S_ * B_ * H_];
__device__ __nv_bfloat16 g_h16f[(size_t)S_ * B_ * H_];  // bf16 h for scan exchange
__device__ __nv_bfloat16 g_h16b[(size_t)S_ * B_ * H_];
// per-producer monotonic flags: [dir][bhalf][jblk][pad]
__device__ unsigned g_flag[2][2][32][8];

// ---------------- common helpers ----------------
__device__ __forceinline__ void mma_tf32(float c[4],
    uint32_t a0, uint32_t a1, uint32_t a2, uint32_t a3,
    uint32_t b0, uint32_t b1)
{
    asm volatile(
        "mma.sync.aligned.m16n8k8.row.col.f32.tf32.tf32.f32 "
        "{%0,%1,%2,%3},{%4,%5,%6,%7},{%8,%9},{%0,%1,%2,%3};"
        : "+f"(c[0]), "+f"(c[1]), "+f"(c[2]), "+f"(c[3])
        : "r"(a0), "r"(a1), "r"(a2), "r"(a3), "r"(b0), "r"(b1));
}

__device__ __forceinline__ void mma_bf16(float c[4],
    uint32_t a0, uint32_t a1, uint32_t a2, uint32_t a3,
    uint32_t b0, uint32_t b1)
{
    asm volatile(
        "mma.sync.aligned.m16n8k16.row.col.f32.bf16.bf16.f32 "
        "{%0,%1,%2,%3},{%4,%5,%6,%7},{%8,%9},{%0,%1,%2,%3};"
        : "+f"(c[0]), "+f"(c[1]), "+f"(c[2]), "+f"(c[3])
        : "r"(a0), "r"(a1), "r"(a2), "r"(a3), "r"(b0), "r"(b1));
}

__device__ __forceinline__ uint32_t pack_bf16(float lo, float hi) {
    uint32_t r;
    asm("cvt.rn.bf16x2.f32 %0, %1, %2;" : "=r"(r) : "f"(hi), "f"(lo));
    return r;
}

__device__ __forceinline__ unsigned ld_acquire(unsigned* p) {
    unsigned v;
    asm volatile("ld.acquire.gpu.global.u32 %0,[%1];" : "=r"(v) : "l"(p) : "memory");
    return v;
}

__device__ __forceinline__ void st_release(unsigned* p, unsigned v) {
    asm volatile("st.release.gpu.global.u32 [%0],%1;" :: "l"(p), "r"(v) : "memory");
}

__device__ __forceinline__ uint32_t smem_u32(const void* p) {
    uint32_t a;
    asm("{ .reg .u64 t; cvta.to.shared.u64 t, %1; cvt.u32.u64 %0, t; }"
        : "=r"(a) : "l"(p));
    return a;
}

__device__ __forceinline__ void cp_async16(uint32_t dst, const void* src, unsigned srcbytes) {
    asm volatile("cp.async.cg.shared.global [%0], [%1], 16, %2;"
                 :: "r"(dst), "l"(src), "r"(srcbytes));
}

__device__ __forceinline__ float sigm_f(float x) {
    return __fdividef(1.f, 1.f + __expf(-x));
}
__device__ __forceinline__ float tanh_f(float x) {
    const float ax = fabsf(x);
    const float e  = __expf(-2.f * ax);
    const float r  = __fdividef(1.f - e, 1.f + e);
    return copysignf(r, x);
}

// =================================================================================
// Kernel A: gi = gather(emb, idx) @ W_ih^T + b_ih — tf32 MMA, cp.async 2-stage
// pipeline. M=16384, N=3072, K=300 (19 tiles of 16). smem [row][k] pitch 20 u32
// (conflict-free for both cp.async stores and fragment LDS). Raw fp32 bits as
// tf32 operands (HW truncation).
// =================================================================================
#define TKP 20

__global__ void __launch_bounds__(256, 2) gi_gemm_kernel(
    const int* __restrict__ idxmat, const float* __restrict__ emb,
    const float* __restrict__ Wf, const float* __restrict__ bf,
    const float* __restrict__ Wb, const float* __restrict__ bbias)
{
    __shared__ uint32_t As[2][128][TKP];
    __shared__ uint32_t Bs[2][128][TKP];

    const int t    = threadIdx.x;
    const int n0   = blockIdx.x * 128;
    const int m0   = blockIdx.y * 128;
    const bool bwd = (n0 >= G3);

    const int lr = t & 127;       // row this thread copies
    const int kh = t >> 7;        // k-half (0 or 1): k offsets 8*kh + {0,4}

    const int am = m0 + lr;
    const int srow = am >> 6, brow = am & 63;
    const float* arow = emb + (size_t)idxmat[brow * S_ + srow] * E_;

    const int ng = n0 + lr;
    const float* wrow = bwd ? (Wb + (size_t)(ng - G3) * E_)
                            : (Wf + (size_t)ng * E_);

    const int lane = t & 31;
    const int w    = t >> 5;
    const int gq   = lane >> 2, tig = lane & 3;
    const int mw   = (w & 3) * 32;
    const int nw   = (w >> 2) * 64;

    float acc[2][8][4];
#pragma unroll
    for (int mt = 0; mt < 2; mt++)
#pragma unroll
        for (int nt = 0; nt < 8; nt++)
#pragma unroll
            for (int i = 0; i < 4; i++) acc[mt][nt][i] = 0.f;

    const uint32_t sA0 = smem_u32(&As[0][lr][8 * kh]);
    const uint32_t sB0 = smem_u32(&Bs[0][lr][8 * kh]);
    const uint32_t bstr = 128 * TKP * 4;   // bytes per buffer

    // prologue: tile 0
    {
        const int ka = 8 * kh;
        const unsigned p0 = (ka < E_) ? 16u : 0u;
        const unsigned p1 = (ka + 4 < E_) ? 16u : 0u;
        cp_async16(sA0,      arow + ka,     p0);
        cp_async16(sA0 + 16, arow + ka + 4, p1);
        cp_async16(sB0,      wrow + ka,     p0);
        cp_async16(sB0 + 16, wrow + ka + 4, p1);
        asm volatile("cp.async.commit_group;");
    }

    for (int tile = 0; tile < 19; tile++) {
        if (tile + 1 < 19) {
            const int bi = (tile + 1) & 1;
            const int ka = (tile + 1) * 16 + 8 * kh;
            const unsigned p0 = (ka < E_) ? 16u : 0u;
            const unsigned p1 = (ka + 4 < E_) ? 16u : 0u;
            cp_async16(sA0 + bi * bstr,      arow + ka,     p0);
            cp_async16(sA0 + bi * bstr + 16, arow + ka + 4, p1);
            cp_async16(sB0 + bi * bstr,      wrow + ka,     p0);
            cp_async16(sB0 + bi * bstr + 16, wrow + ka + 4, p1);
        }
        asm volatile("cp.async.commit_group;");
        asm volatile("cp.async.wait_group 1;");
        __syncthreads();

        const int bi = tile & 1;
#pragma unroll
        for (int kt = 0; kt < 2; kt++) {
            const int kb = kt * 8;
            uint32_t a[2][4];
#pragma unroll
            for (int mt = 0; mt < 2; mt++) {
                const int mb = mw + mt * 16;
                a[mt][0] = As[bi][mb + gq][kb + tig];
                a[mt][1] = As[bi][mb + gq + 8][kb + tig];
                a[mt][2] = As[bi][mb + gq][kb + tig + 4];
                a[mt][3] = As[bi][mb + gq + 8][kb + tig + 4];
            }
#pragma unroll
            for (int nt = 0; nt < 8; nt++) {
                const int nb = nw + nt * 8 + gq;
                const uint32_t b0v = Bs[bi][nb][kb + tig];
                const uint32_t b1v = Bs[bi][nb][kb + tig + 4];
                mma_tf32(acc[0][nt], a[0][0], a[0][1], a[0][2], a[0][3], b0v, b1v);
                mma_tf32(acc[1][nt], a[1][0], a[1][1], a[1][2], a[1][3], b0v, b1v);
            }
        }
        __syncthreads();
    }

    const float* bias = bwd ? bbias : bf;
    float* gbase = bwd ? g_gi_b : g_gi_f;
    const int nc0 = (bwd ? n0 - G3 : n0) + nw;

#pragma unroll
    for (int mt = 0; mt < 2; mt++) {
#pragma unroll
        for (int half = 0; half < 2; half++) {
            const int rm = m0 + mw + mt * 16 + gq + half * 8;
            const int si = rm >> 6, bi2 = rm & 63;
            const size_t mrow = bwd ? ((size_t)(S_ - 1 - si) * B_ + bi2) : (size_t)rm;
            float* dst = gbase + mrow * G3;
#pragma unroll
            for (int nt = 0; nt < 8; nt++) {
                const int c = nc0 + nt * 8 + 2 * tig;
                float2 v;
                v.x = acc[mt][nt][half * 2 + 0] + bias[c];
                v.y = acc[mt][nt][half * 2 + 1] + bias[c + 1];
                *(float2*)(dst + c) = v;
            }
        }
    }
}

// =================================================================================
// Kernel B: persistent bidirectional GRU scan — bf16 mma, per-producer flags,
// direct gmem->register B-fragments (no smem staging on the critical path).
// 128 blocks = dir(2) x jblk(32) x bhalf(2). 8 warps = k-eighth.
// =================================================================================
#define BUFP 34
#define HOLDP 17
#define SMEM_B_BYTES ((8 * 48 * BUFP + 32 * HOLDP + 64) * 4)

__global__ void __launch_bounds__(256, 1) gru_scan_kernel(
    const float* __restrict__ Whh_f, const float* __restrict__ bhh_f,
    const float* __restrict__ Whh_b, const float* __restrict__ bhh_b)
{
    extern __shared__ float sm[];
    float* buf  = sm;                        // [8*48][BUFP] mma partials
    float* hold = buf + 8 * 48 * BUFP;       // [32][HOLDP] own fp32 h_prev slice
    __shared__ float bbv[48];
    __shared__ unsigned sbase;

    const int t    = threadIdx.x;
    const int lane = t & 31;
    const int kg   = t >> 5;          // warp = k-eighth 0..7
    const int gq   = lane >> 2;
    const int tig  = lane & 3;

    const int blk   = blockIdx.x;
    const int dir   = blk >> 6;
    const int r     = blk & 63;
    const int jblk  = r >> 1;
    const int bhalf = r & 1;
    const int j0    = jblk * 16;
    const int b0    = bhalf * 32;

    const float* Whh = dir ? Whh_b : Whh_f;
    const float* bhh = dir ? bhh_b : bhh_f;
    const float* gi  = dir ? g_gi_b : g_gi_f;
    float* hout32    = dir ? g_hb : g_hf;
    __nv_bfloat16* hout16 = dir ? g_h16b : g_h16f;

    if (t < 48) bbv[t] = bhh[(size_t)((t >> 4) * 512 + j0 + (t & 15))];
    if (t == 0) sbase = *(volatile unsigned*)&g_flag[dir][bhalf][jblk][0];

    // ---- register-resident bf16 A-fragments: a[g][kt][4] ----
    uint32_t a[3][4][4];
#pragma unroll
    for (int g = 0; g < 3; g++) {
        const float* Wg = Whh + (size_t)(g * 512 + j0) * 512;
#pragma unroll
        for (int kt = 0; kt < 4; kt++) {
            const int kb = kg * 64 + kt * 16;
            const int c0 = kb + 2 * tig;
            const int c1 = kb + 8 + 2 * tig;
            a[g][kt][0] = pack_bf16(Wg[(size_t)gq * 512 + c0],      Wg[(size_t)gq * 512 + c0 + 1]);
            a[g][kt][1] = pack_bf16(Wg[(size_t)(gq + 8) * 512 + c0], Wg[(size_t)(gq + 8) * 512 + c0 + 1]);
            a[g][kt][2] = pack_bf16(Wg[(size_t)gq * 512 + c1],      Wg[(size_t)gq * 512 + c1 + 1]);
            a[g][kt][3] = pack_bf16(Wg[(size_t)(gq + 8) * 512 + c1], Wg[(size_t)(gq + 8) * 512 + c1 + 1]);
        }
    }
    __syncthreads();

    const unsigned sb = sbase;

    // gate-combine coordinates: thread -> (j1, batch pair 2m/2m+1)
    const int j1 = t & 15;
    const int m_ = t >> 4;            // 0..15
    const int bA = 2 * m_, bB = 2 * m_ + 1;

    for (int s = 0; s < S_; ++s) {
        // ---- prefetch gi[s] (overlaps flag wait) ----
        const float* gis = gi + (size_t)s * (B_ * G3);
        const size_t gaA = (size_t)(b0 + bA) * G3 + j0 + j1;
        const size_t gaB = (size_t)(b0 + bB) * G3 + j0 + j1;
        const float irA = gis[gaA], izA = gis[gaA + 512], inA = gis[gaA + 1024];
        const float irB = gis[gaB], izB = gis[gaB + 512], inB = gis[gaB + 1024];

        if (s > 0) {
            // ---- per-warp: wait for this warp's 4 producer blocks only ----
            const unsigned tgt = sb + (unsigned)s;
            if (lane < 4) {
                unsigned* fp = &g_flag[dir][bhalf][4 * kg + lane][0];
                while (ld_acquire(fp) < tgt) { }
            }
            __syncwarp();

            // ---- B-fragments straight from gmem (no staging) ----
            const uint32_t* hbase = (const uint32_t*)(hout16
                + (size_t)(s - 1) * (B_ * H_) + (size_t)b0 * H_);
            uint32_t bb[4][4][2];     // [nt][kt][2]
#pragma unroll
            for (int nt = 0; nt < 4; nt++) {
                const uint32_t* hr = hbase + (size_t)(nt * 8 + gq) * (H_ / 2)
                                     + kg * 32 + tig;
#pragma unroll
                for (int kt = 0; kt < 4; kt++) {
                    bb[nt][kt][0] = hr[kt * 8];
                    bb[nt][kt][1] = hr[kt * 8 + 4];
                }
            }

            float acc[3][4][4];
#pragma unroll
            for (int g = 0; g < 3; g++)
#pragma unroll
                for (int nt = 0; nt < 4; nt++)
#pragma unroll
                    for (int i = 0; i < 4; i++) acc[g][nt][i] = 0.f;

#pragma unroll
            for (int kt = 0; kt < 4; kt++)
#pragma unroll
                for (int nt = 0; nt < 4; nt++)
#pragma unroll
                    for (int g = 0; g < 3; g++)
                        mma_bf16(acc[g][nt], a[g][kt][0], a[g][kt][1],
                                 a[g][kt][2], a[g][kt][3],
                                 bb[nt][kt][0], bb[nt][kt][1]);

#pragma unroll
            for (int g = 0; g < 3; g++) {
                float* bbp = buf + (size_t)(kg * 48 + g * 16) * BUFP;
#pragma unroll
                for (int nt = 0; nt < 4; nt++) {
                    const int c = nt * 8 + 2 * tig;
                    *(float2*)(bbp + gq * BUFP + c)       = make_float2(acc[g][nt][0], acc[g][nt][1]);
                    *(float2*)(bbp + (gq + 8) * BUFP + c) = make_float2(acc[g][nt][2], acc[g][nt][3]);
                }
            }
            __syncthreads();
        }

        // ---- gate combine: batch pair (bA, bB) per thread, float2 reductions ----
        float* hnew32 = hout32 + (size_t)s * (B_ * H_);
        __nv_bfloat16* hnew16 = hout16 + (size_t)s * (B_ * H_);

        float rsA = 0.f, zsA = 0.f, nsA = 0.f, hpA = 0.f;
        float rsB = 0.f, zsB = 0.f, nsB = 0.f, hpB = 0.f;
        if (s > 0) {
#pragma unroll
            for (int q = 0; q < 8; q++) {
                const float2 vr = *(const float2*)(buf + (q * 48 + j1) * BUFP + bA);
                const float2 vz = *(const float2*)(buf + (q * 48 + 16 + j1) * BUFP + bA);
                const float2 vn = *(const float2*)(buf + (q * 48 + 32 + j1) * BUFP + bA);
                rsA += vr.x; rsB += vr.y;
                zsA += vz.x; zsB += vz.y;
                nsA += vn.x; nsB += vn.y;
            }
            hpA = hold[bA * HOLDP + j1];
            hpB = hold[bB * HOLDP + j1];
        }
        {
            const float rg = sigm_f(irA + rsA + bbv[j1]);
            const float zg = sigm_f(izA + zsA + bbv[16 + j1]);
            const float ng = tanh_f(inA + rg * (nsA + bbv[32 + j1]));
            const float hv = (1.f - zg) * ng + zg * hpA;
            hnew32[(size_t)(b0 + bA) * H_ + j0 + j1] = hv;
            hnew16[(size_t)(b0 + bA) * H_ + j0 + j1] = __float2bfloat16(hv);
            hold[bA * HOLDP + j1] = hv;
        }
        {
            const float rg = sigm_f(irB + rsB + bbv[j1]);
            const float zg = sigm_f(izB + zsB + bbv[16 + j1]);
            const float ng = tanh_f(inB + rg * (nsB + bbv[32 + j1]));
            const float hv = (1.f - zg) * ng + zg * hpB;
            hnew32[(size_t)(b0 + bB) * H_ + j0 + j1] = hv;
            hnew16[(size_t)(b0 + bB) * H_ + j0 + j1] = __float2bfloat16(hv);
            hold[bB * HOLDP + j1] = hv;
        }

        // ---- publish own slice: one release store, no atomics ----
        if (s < S_ - 1) {
            __syncthreads();
            if (t == 0)
                st_release(&g_flag[dir][bhalf][jblk][0], sb + (unsigned)s + 1u);
        }
    }
}

// =================================================================================
// Kernel C: logits + log_softmax + transpose to [B,21,S].
// 2048 blocks x 8 rows; float4 W fill.
// =================================================================================
#define SMEM_C_BYTES ((NCLS * 1024 + 1024 + 32) * 4)

__global__ void __launch_bounds__(256, 1) head_kernel(
    const float* __restrict__ linW, const float* __restrict__ linb,
    float* __restrict__ out)
{
    extern __shared__ float sm[];
    float* Wsm = sm;
    float* row = Wsm + NCLS * 1024;
    float* lg  = row + 1024;

    const int t = threadIdx.x;
    for (int i = t; i < NCLS * 256; i += 256)
        ((float4*)Wsm)[i] = ((const float4*)linW)[i];
    __syncthreads();

    const int w = t >> 5, lane = t & 31;
    const int m0 = blockIdx.x * 8;

    for (int rr = 0; rr < 8; rr++) {
        const int m = m0 + rr;
        const int s = m >> 6, b = m & 63;
        const float* hf = g_hf + ((size_t)s * B_ + b) * H_;
        const float* hb = g_hb + ((size_t)(S_ - 1 - s) * B_ + b) * H_;
        ((float4*)row)[t] = (t < 128) ? ((const float4*)hf)[t]
                                      : ((const float4*)hb)[t - 128];
        __syncthreads();

#pragma unroll
        for (int j = 0; j < 3; j++) {
            const int c = w + 8 * j;
            if (c < NCLS) {
                float p = 0.f;
                const float* wc = Wsm + c * 1024;
#pragma unroll 4
                for (int k = lane; k < 1024; k += 32) p = fmaf(row[k], wc[k], p);
#pragma unroll
                for (int off = 16; off; off >>= 1) p += __shfl_xor_sync(0xffffffffu, p, off);
                if (lane == 0) lg[c] = p + linb[c];
            }
        }
        __syncthreads();
        if (t == 0) {
            float mx = lg[0];
            for (int c = 1; c < NCLS; c++) mx = fmaxf(mx, lg[c]);
            float sum = 0.f;
            for (int c = 0; c < NCLS; c++) sum += __expf(lg[c] - mx);
            lg[24] = mx + __logf(sum);
        }
        __syncthreads();
        if (t < NCLS)
            out[(size_t)b * (NCLS * S_) + (size_t)t * S_ + s] = lg[t] - lg[24];
        __syncthreads();
    }
}

// =================================================================================
extern "C" void kernel_launch(void* const* d_in, const int* in_sizes, int n_in,
                              void* d_out, int out_size)
{
    (void)in_sizes; (void)n_in; (void)out_size;
    const int*   idx     = (const int*)  d_in[0];
    const float* emb     = (const float*)d_in[1];
    const float* W_ih_f  = (const float*)d_in[2];
    const float* W_hh_f  = (const float*)d_in[3];
    const float* b_ih_f  = (const float*)d_in[4];
    const float* b_hh_f  = (const float*)d_in[5];
    const float* W_ih_b  = (const float*)d_in[6];
    const float* W_hh_b  = (const float*)d_in[7];
    const float* b_ih_b  = (const float*)d_in[8];
    const float* b_hh_b  = (const float*)d_in[9];
    const float* lin_W   = (const float*)d_in[10];
    const float* lin_b   = (const float*)d_in[11];
    float* out = (float*)d_out;

    cudaFuncSetAttribute(gru_scan_kernel, cudaFuncAttributeMaxDynamicSharedMemorySize, SMEM_B_BYTES);
    cudaFuncSetAttribute(head_kernel,     cudaFuncAttributeMaxDynamicSharedMemorySize, SMEM_C_BYTES);

    dim3 gA(24, 128);
    gi_gemm_kernel<<<gA, 256>>>(idx, emb, W_ih_f, b_ih_f, W_ih_b, b_ih_b);
    gru_scan_kernel<<<128, 256, SMEM_B_BYTES>>>(W_hh_f, b_hh_f, W_hh_b, b_hh_b);
    head_kernel<<<2048, 256, SMEM_C_BYTES>>>(lin_W, lin_b, out);
}